// round 1
// baseline (speedup 1.0000x reference)
#include <cuda_runtime.h>

// Problem shape (fixed by setup_inputs): x (B=8, S=4096, D=1024) fp32.
// Reference: per row s of x[0], scan over feature dim:
//   m_i = (m_{i-1} + d_i) / i ;  v += (d_i - m_i)^2   (i = 1..D)
//   var = v / (D-1);  out[b,s,d] = alpha[d]*(x[b,s,d]-m)/sqrt(var+eps)+beta[d]

#define S_DIM 4096
#define D_DIM 1024
#define EPSV  1e-5f

__device__ float g_mean[S_DIM];
__device__ float g_rstd[S_DIM];

// ---------------- Kernel 1: per-row sequential scan (stats) ----------------
// One thread per row of x[0]. Critical path per step is a single FFMA:
//   m = fma(m, rinv_i, d_i * rinv_i)
// Reciprocals 1/i precomputed into shared memory (broadcast LDS per step).
__global__ void ln_scan_kernel(const float* __restrict__ x0) {
    __shared__ __align__(16) float rinv[D_DIM];
    for (int i = threadIdx.x; i < D_DIM; i += blockDim.x)
        rinv[i] = 1.0f / (float)(i + 1);
    __syncthreads();

    const int row = blockIdx.x * blockDim.x + threadIdx.x;
    if (row >= S_DIM) return;

    const float4* __restrict__ xr  = (const float4*)(x0 + (size_t)row * D_DIM);
    const float4* __restrict__ rv4 = (const float4*)rinv;

    float m = 0.0f, v = 0.0f;

#define LN_STEP(dv, rr)                         \
    do {                                        \
        m = fmaf(m, (rr), (dv) * (rr));         \
        float t = (dv) - m;                     \
        v = fmaf(t, t, v);                      \
    } while (0)

#pragma unroll 4
    for (int i = 0; i < D_DIM / 4; ++i) {
        float4 d = xr[i];
        float4 r = rv4[i];
        LN_STEP(d.x, r.x);
        LN_STEP(d.y, r.y);
        LN_STEP(d.z, r.z);
        LN_STEP(d.w, r.w);
    }
#undef LN_STEP

    v = v / (float)(D_DIM - 1);
    g_mean[row] = m;
    g_rstd[row] = rsqrtf(v + EPSV);
}

// ---------------- Kernel 2: streaming normalize (memory-bound) -------------
// out = alpha * (x - mean[s]) * rstd[s] + beta, float4 per thread.
__global__ void ln_norm_kernel(const float* __restrict__ x,
                               const float* __restrict__ alpha,
                               const float* __restrict__ beta,
                               float* __restrict__ out,
                               long long n4) {
    long long idx = (long long)blockIdx.x * blockDim.x + threadIdx.x;
    if (idx >= n4) return;

    const int d4 = (int)(idx & (D_DIM / 4 - 1));          // float4 index within row
    const int s  = (int)((idx >> 8) & (S_DIM - 1));       // D_DIM/4 == 256 == 1<<8

    const float m  = g_mean[s];
    const float rs = g_rstd[s];

    float4 xv = ((const float4*)x)[idx];
    float4 a  = ((const float4*)alpha)[d4];
    float4 b  = ((const float4*)beta)[d4];

    float4 o;
    o.x = fmaf((xv.x - m) * rs, a.x, b.x);
    o.y = fmaf((xv.y - m) * rs, a.y, b.y);
    o.z = fmaf((xv.z - m) * rs, a.z, b.z);
    o.w = fmaf((xv.w - m) * rs, a.w, b.w);

    ((float4*)out)[idx] = o;
}

extern "C" void kernel_launch(void* const* d_in, const int* in_sizes, int n_in,
                              void* d_out, int out_size) {
    const float* x     = (const float*)d_in[0];
    const float* alpha = (const float*)d_in[1];
    const float* beta  = (const float*)d_in[2];
    float*       out   = (float*)d_out;

    // B derived from input size; S, D fixed by problem shape.
    const long long total = (long long)in_sizes[0];       // B*S*D
    const long long n4    = total / 4;                    // float4 count

    // Stats over x[0] (first S*D floats): 4096 rows, 1 thread each.
    ln_scan_kernel<<<S_DIM / 128, 128>>>(x);

    // Streaming normalize over all B*S*D elements.
    const int threads = 256;
    const long long blocks = (n4 + threads - 1) / threads;
    ln_norm_kernel<<<(unsigned)blocks, threads>>>(x, alpha, beta, out, n4);
}

// round 2
// speedup vs baseline: 1.4612x; 1.4612x over previous
#include <cuda_runtime.h>

// Shape fixed by setup_inputs: x (B=8, S=4096, D=1024) fp32.
// Stats come from a SEQUENTIAL scan over D of x[0] only:
//   m_i = (m_{i-1} + d_i) / i ;  v += (d_i - m_i)^2 ;  var = v/(D-1)
// then out[b,s,d] = alpha[d]*(x[b,s,d]-m_s)/sqrt(var_s+eps)+beta[d]

#define S_DIM 4096
#define D_DIM 1024
#define EPSV  1e-5f

#define ROWS_PB      64            // rows per block (scan kernel)
#define CHUNK        64            // floats per row per chunk
#define NCHUNK       (D_DIM / CHUNK)   // 16
#define SCAN_THREADS 128
#define SSTRIDE      (CHUNK + 1)   // padded smem row stride (conflict-free)

__device__ float g_mean[S_DIM];
__device__ float g_rstd[S_DIM];

// ---------------- Kernel 1: coalesced-staged sequential scan ----------------
// 64 blocks x 128 threads; each block owns 64 rows of x[0].
// Per chunk: all 128 threads load 64x64 floats coalesced (float4) into regs,
// store to padded smem tile, then threads 0..63 advance their row's recurrence
// from smem. Next chunk's gmem loads are issued BEFORE the scan barrier so
// DRAM latency overlaps the FFMA dependency chain.
__global__ __launch_bounds__(SCAN_THREADS)
void ln_scan_kernel(const float* __restrict__ x0) {
    __shared__ float tile[ROWS_PB * SSTRIDE];
    __shared__ float rinv[D_DIM];

    const int tid = threadIdx.x;
    for (int i = tid; i < D_DIM; i += SCAN_THREADS)
        rinv[i] = 1.0f / (float)(i + 1);

    const int rowBase = blockIdx.x * ROWS_PB;
    const int lrow = tid >> 4;          // 0..7  : row group offset
    const int q    = tid & 15;          // 0..15 : float4 column within chunk
    const float4* __restrict__ xr = (const float4*)x0;   // 256 float4 per row

    float4 buf[8];
#pragma unroll
    for (int k = 0; k < 8; ++k) {
        int r = lrow + k * 8;
        buf[k] = xr[(size_t)(rowBase + r) * 256 + q];
    }

    float m = 0.0f, v = 0.0f;

    for (int c = 0; c < NCHUNK; ++c) {
        __syncthreads();                 // smem tile free (and rinv ready at c==0)
#pragma unroll
        for (int k = 0; k < 8; ++k) {
            int r = lrow + k * 8;
            float* dst = &tile[r * SSTRIDE + q * 4];
            dst[0] = buf[k].x; dst[1] = buf[k].y;
            dst[2] = buf[k].z; dst[3] = buf[k].w;
        }
        if (c + 1 < NCHUNK) {            // prefetch next chunk (overlaps scan)
#pragma unroll
            for (int k = 0; k < 8; ++k) {
                int r = lrow + k * 8;
                buf[k] = xr[(size_t)(rowBase + r) * 256 + (c + 1) * 16 + q];
            }
        }
        __syncthreads();                 // tile ready

        if (tid < ROWS_PB) {
            const float* __restrict__ src = &tile[tid * SSTRIDE];
            const float* __restrict__ rv  = &rinv[c * CHUNK];
#pragma unroll
            for (int j = 0; j < CHUNK; ++j) {
                float d = src[j];
                float r = rv[j];
                m = fmaf(m, r, d * r);   // (m + d) / i, single-FFMA chain
                float t = d - m;
                v = fmaf(t, t, v);       // off critical path
            }
        }
    }

    if (tid < ROWS_PB) {
        v = v / (float)(D_DIM - 1);
        g_mean[rowBase + tid] = m;
        g_rstd[rowBase + tid] = rsqrtf(v + EPSV);
    }
}

// ---------------- Kernel 2: streaming normalize (HBM-bound) -----------------
// 2 float4 per thread, non-temporal load/store hints for the streamed tensors.
__global__ __launch_bounds__(256)
void ln_norm_kernel(const float* __restrict__ x,
                    const float* __restrict__ alpha,
                    const float* __restrict__ beta,
                    float* __restrict__ out,
                    long long n4) {
    const long long i0 = (long long)blockIdx.x * 512 + threadIdx.x;

#pragma unroll
    for (int u = 0; u < 2; ++u) {
        long long idx = i0 + u * 256;
        if (idx < n4) {
            const int d4 = (int)(idx & (D_DIM / 4 - 1));
            const int s  = (int)((idx >> 8) & (S_DIM - 1));

            const float m  = g_mean[s];
            const float rs = g_rstd[s];

            float4 xv = __ldcs(((const float4*)x) + idx);
            float4 a  = __ldg(((const float4*)alpha) + d4);
            float4 b  = __ldg(((const float4*)beta) + d4);

            float4 o;
            o.x = fmaf((xv.x - m) * rs, a.x, b.x);
            o.y = fmaf((xv.y - m) * rs, a.y, b.y);
            o.z = fmaf((xv.z - m) * rs, a.z, b.z);
            o.w = fmaf((xv.w - m) * rs, a.w, b.w);

            __stcs(((float4*)out) + idx, o);
        }
    }
}

extern "C" void kernel_launch(void* const* d_in, const int* in_sizes, int n_in,
                              void* d_out, int out_size) {
    const float* x     = (const float*)d_in[0];
    const float* alpha = (const float*)d_in[1];
    const float* beta  = (const float*)d_in[2];
    float*       out   = (float*)d_out;

    const long long total = (long long)in_sizes[0];   // B*S*D
    const long long n4    = total / 4;

    ln_scan_kernel<<<S_DIM / ROWS_PB, SCAN_THREADS>>>(x);

    const long long blocks = (n4 + 511) / 512;
    ln_norm_kernel<<<(unsigned)blocks, 256>>>(x, alpha, beta, out, n4);
}

// round 3
// speedup vs baseline: 1.7703x; 1.2115x over previous
#include <cuda_runtime.h>

// Shape fixed by setup_inputs: x (B=8, S=4096, D=1024) fp32.
// Stats from sequential scan over D of x[0]:
//   m_i = (m_{i-1} + d_i)/i ;  v += (d_i - m_i)^2 ;  var = v/(D-1)
// The recurrence's state decays by 1/i per step (factorial forgetting), so a
// 16-step warm-up makes per-segment restarts exact to ~1e-20 — the scan is
// warp-parallel. Fully fused: one block per row computes stats then streams
// all B batches of that row.

#define S_DIM 4096
#define D_DIM 1024
#define EPSV  1e-5f
#define WARM  16

__global__ __launch_bounds__(256)
void ln_fused_kernel(const float* __restrict__ x,
                     const float* __restrict__ alpha,
                     const float* __restrict__ beta,
                     float* __restrict__ out,
                     int B) {
    __shared__ float row[D_DIM + D_DIM / 32];   // swizzle: off = idx + (idx>>5)
    __shared__ float s_stats[2];                // [0]=mean, [1]=rstd

    const int s   = blockIdx.x;
    const int tid = threadIdx.x;

    // ---- Phase 1: coalesced load of x[0,s,:] into swizzled smem ----
    {
        float4 v = __ldg(((const float4*)(x + (size_t)s * D_DIM)) + tid);
        int base = tid * 4;                     // base%32 in {0,4,...,28}: no pad crossing
        int o = base + (base >> 5);
        row[o]   = v.x; row[o+1] = v.y;
        row[o+2] = v.z; row[o+3] = v.w;
    }
    __syncthreads();

    // ---- Phase 2: warp 0 segment-parallel scan (32 lanes x 32 elements) ----
    if (tid < 32) {
        const int L     = tid;
        const int start = L * 32;
        float m = 0.0f, v = 0.0f;

        if (L > 0) {                            // warm-up: rebuilds m to ~1e-20 accuracy
#pragma unroll
            for (int j = WARM; j > 0; --j) {
                int idx = start - j;
                float d = row[idx + (idx >> 5)];
                float r = __fdividef(1.0f, (float)(idx + 1));
                m = fmaf(m, r, d * r);
            }
        }
#pragma unroll
        for (int j = 0; j < 32; ++j) {
            int idx = start + j;
            float d = row[idx + (idx >> 5)];
            float r = __fdividef(1.0f, (float)(idx + 1));
            m = fmaf(m, r, d * r);              // (m + d)/i
            float t = d - m;
            v = fmaf(t, t, v);                  // per-lane var partial
        }
#pragma unroll
        for (int o = 16; o; o >>= 1)
            v += __shfl_xor_sync(0xffffffffu, v, o);
        float mean = __shfl_sync(0xffffffffu, m, 31);   // final m at i = D
        if (L == 0) {
            s_stats[0] = mean;
            s_stats[1] = rsqrtf(v / (float)(D_DIM - 1) + EPSV);
        }
    }
    __syncthreads();

    // ---- Phase 3: stream-normalize all B batches of row s ----
    const float m  = s_stats[0];
    const float rs = s_stats[1];

    const float4 a = __ldg(((const float4*)alpha) + tid);   // tid = float4 col (0..255)
    const float4 b = __ldg(((const float4*)beta)  + tid);

#pragma unroll 8
    for (int bb = 0; bb < B; ++bb) {
        size_t idx = ((size_t)bb * S_DIM + (size_t)s) * (D_DIM / 4) + tid;
        float4 xv = __ldcs(((const float4*)x) + idx);
        float4 o;
        o.x = fmaf((xv.x - m) * rs, a.x, b.x);
        o.y = fmaf((xv.y - m) * rs, a.y, b.y);
        o.z = fmaf((xv.z - m) * rs, a.z, b.z);
        o.w = fmaf((xv.w - m) * rs, a.w, b.w);
        __stcs(((float4*)out) + idx, o);
    }
}

extern "C" void kernel_launch(void* const* d_in, const int* in_sizes, int n_in,
                              void* d_out, int out_size) {
    const float* x     = (const float*)d_in[0];
    const float* alpha = (const float*)d_in[1];
    const float* beta  = (const float*)d_in[2];
    float*       out   = (float*)d_out;

    const int B = in_sizes[0] / (S_DIM * D_DIM);

    ln_fused_kernel<<<S_DIM, 256>>>(x, alpha, beta, out, B);
}